// round 13
// baseline (speedup 1.0000x reference)
#include <cuda_runtime.h>
#include <math.h>

#define BATCH   8
#define NPTS    4096
#define SPLITS  16
#define SCAND   (NPTS / SPLITS)   // 256 candidates per split = one tile
#define TILE    256
#define BLOCK   64
#define Q       8                 // queries per thread
#define QPB     (BLOCK * Q)       // 512 queries per block
#define QCHUNKS_MAIN (NPTS / QPB) // 8
#define CQ      8                 // queries per combine block (one per warp)
#define QCHUNKS (NPTS / CQ)       // 512 combine chunks per (dir,b)
#define NCOMBINE (QCHUNKS * BATCH * 2)  // 8192 combine blocks

// Scratch (static device arrays; no allocation allowed)
__device__ unsigned long long g_pack[2 * BATCH * NPTS * SPLITS]; // (score|base) packed
__device__ float g_part[NCOMBINE];                               // per-chunk |diff|^5 sums
__device__ unsigned int g_ticket;                                // zero-init, self-resetting

// Order-preserving float -> uint32 map (monotone for all finite floats).
static __device__ __forceinline__ unsigned int fmap(float f) {
    unsigned int u = __float_as_uint(f);
    return (u & 0x80000000u) ? ~u : (u | 0x80000000u);
}
static __device__ __forceinline__ float funmap(unsigned int m) {
    return __uint_as_float((m & 0x80000000u) ? (m & 0x7FFFFFFFu) : ~m);
}

// Bit-exact rescore (identical fmaf sequence everywhere it is evaluated).
static __device__ __forceinline__ float score(float cx, float cy, float cz,
                                              float nqx, float nqy, float nqz) {
    float h = 0.5f * fmaf(cx, cx, fmaf(cy, cy, cz * cz));
    return fmaf(nqx, cx, fmaf(nqy, cy, fmaf(nqz, cz, h)));
}

// Main: each thread owns 8 queries, scans this block's 256-candidate split.
// Objective: h - q.c, h = 0.5|c|^2 (|q|^2 dropped, argmin-invariant).
// Writes one packed u64 per (query, split): [mapped score | 32-group base].
// EXACT copy of the round-10 kernel (proven at the FFMA-pipe floor).
__global__ void __launch_bounds__(BLOCK) chamfer_main(
    const float* __restrict__ x, const float* __restrict__ y)
{
    const int qchunk = blockIdx.x >> 4;    // 0..7
    const int split  = blockIdx.x & 15;    // 0..15
    const int b   = blockIdx.y;
    const int dir = blockIdx.z;
    const float* q  = (dir == 0) ? x : y;
    const float* db = (dir == 0) ? y : x;
    const float* qb  = q  + (size_t)b * NPTS * 3;
    const float* dbb = db + (size_t)b * NPTS * 3;

    float nqx[Q], nqy[Q], nqz[Q];
    #pragma unroll
    for (int k = 0; k < Q; k++) {
        const int qi = qchunk * QPB + threadIdx.x + k * BLOCK;
        nqx[k] = -qb[qi*3+0];
        nqy[k] = -qb[qi*3+1];
        nqz[k] = -qb[qi*3+2];
    }

    __shared__ float4 sh[TILE];

    const int cbeg = split * SCAND;
    #pragma unroll
    for (int k = 0; k < TILE / BLOCK; k++) {
        const int cl = threadIdx.x + k * BLOCK;
        const int c  = cbeg + cl;
        float cx = dbb[c*3+0], cy = dbb[c*3+1], cz = dbb[c*3+2];
        sh[cl] = make_float4(cx, cy, cz, 0.5f * fmaf(cx, cx, fmaf(cy, cy, cz * cz)));
    }
    __syncthreads();

    float best[Q];
    int   base[Q];
    #pragma unroll
    for (int k = 0; k < Q; k++) { best[k] = 3.4e38f; base[k] = cbeg; }

    #pragma unroll
    for (int g = 0; g < TILE / 32; g++) {
        float prev[Q];
        #pragma unroll
        for (int k = 0; k < Q; k++) prev[k] = best[k];
        #pragma unroll 8
        for (int j = 0; j < 32; j++) {
            float4 c = sh[g * 32 + j];   // broadcast LDS.128, feeds 8 chains
            #pragma unroll
            for (int k = 0; k < Q; k++)
                best[k] = fminf(best[k],
                    fmaf(nqx[k], c.x, fmaf(nqy[k], c.y, fmaf(nqz[k], c.z, c.w))));
        }
        const int gb = cbeg + g * 32;
        #pragma unroll
        for (int k = 0; k < Q; k++)
            if (best[k] < prev[k]) base[k] = gb;   // strict <: earliest group wins
    }

    const int qs = (dir * BATCH + b) * NPTS;
    #pragma unroll
    for (int k = 0; k < Q; k++) {
        const int qi = qchunk * QPB + threadIdx.x + k * BLOCK;
        g_pack[(qs + qi) * SPLITS + split] =
            ((unsigned long long)fmap(best[k]) << 32) | (unsigned int)base[k];
    }
}

// Combine: ONE WARP PER QUERY.
//   lanes 0-15: load the query's 16 split-u64s (coalesced 128B), shfl-min
//               (equal score bits -> smaller base = earlier split: first-min).
//   all lanes:  score candidate base+lane (coalesced 384B, bit-exact chain),
//               one ballot, ffs -> first exact match = first min; NN coords
//               shfl'd from the hit lane. ONE round instead of 32.
// lane 0 computes |diff|^5 sum; block reduces CQ warps; LAST block (ticket)
// folds all 8192 partials into out[0].
__global__ void __launch_bounds__(32 * CQ) combine_kernel(
    const float* __restrict__ x, const float* __restrict__ y,
    float* __restrict__ out)
{
    const int chunk = blockIdx.x;
    const int b   = blockIdx.y;
    const int dir = blockIdx.z;
    const int warpid = threadIdx.x >> 5;
    const int lane   = threadIdx.x & 31;
    const int qi  = chunk * CQ + warpid;
    const float* q  = (dir == 0) ? x : y;
    const float* db = (dir == 0) ? y : x;
    const float* qb  = q  + (size_t)b * NPTS * 3;
    const float* dbb = db + (size_t)b * NPTS * 3;

    // Warp-cooperative split min.
    const int slot = ((dir * BATCH + b) * NPTS + qi) * SPLITS;
    unsigned long long w = (lane < SPLITS) ? g_pack[slot + lane]
                                           : 0xFFFFFFFFFFFFFFFFull;
    #pragma unroll
    for (int off = 16; off > 0; off >>= 1) {
        unsigned long long o = __shfl_down_sync(0xFFFFFFFFu, w, off);
        w = (o < w) ? o : w;
    }
    w = __shfl_sync(0xFFFFFFFFu, w, 0);
    const float bb  = funmap((unsigned int)(w >> 32));
    const int  base = (int)(w & 0xFFFFFFFFu);

    // Query coords: same address across lanes -> broadcast loads.
    const float qx = qb[qi*3+0], qy = qb[qi*3+1], qz = qb[qi*3+2];

    // One-shot rescan: lane j scores candidate base+j (coalesced 384B).
    const int c = base + lane;
    const float cx = dbb[c*3+0], cy = dbb[c*3+1], cz = dbb[c*3+2];
    const float d = score(cx, cy, cz, -qx, -qy, -qz);
    const unsigned int mask = __ballot_sync(0xFFFFFFFFu, d == bb);
    const int first = __ffs(mask) - 1;       // >=0 guaranteed (bit-exact)
    const float nx = __shfl_sync(0xFFFFFFFFu, cx, first);
    const float ny = __shfl_sync(0xFFFFFFFFu, cy, first);
    const float nz = __shfl_sync(0xFFFFFFFFu, cz, first);

    __shared__ float sred[CQ];
    if (lane == 0) {
        float ax = fabsf(qx - nx), ay = fabsf(qy - ny), az = fabsf(qz - nz);
        float ax2 = ax * ax, ay2 = ay * ay, az2 = az * az;
        sred[warpid] = ax2 * ax2 * ax + ay2 * ay2 * ay + az2 * az2 * az;
    }
    __syncthreads();

    __shared__ bool s_last;
    if (warpid == 0) {
        float r = (lane < CQ) ? sred[lane] : 0.0f;
        #pragma unroll
        for (int off = 4; off > 0; off >>= 1)
            r += __shfl_down_sync(0xFFFFFFFFu, r, off);
        if (lane == 0) {
            g_part[(dir * BATCH + b) * QCHUNKS + chunk] = r;
            __threadfence();
            unsigned int t = atomicAdd(&g_ticket, 1u);
            s_last = (t == NCOMBINE - 1);
        }
    }
    __syncthreads();

    if (s_last) {
        // Final fold in the last-arriving block (256 threads, 8192 partials).
        __shared__ float psum[32 * CQ];
        __shared__ float roots[2 * BATCH];
        float s = 0.0f;
        #pragma unroll 4
        for (int i = 0; i < NCOMBINE / (32 * CQ); i++)
            s += g_part[threadIdx.x * (NCOMBINE / (32 * CQ)) + i];
        psum[threadIdx.x] = s;   // psum[t] belongs to strip t/16
        __syncthreads();
        if (threadIdx.x < 2 * BATCH) {
            float ss = 0.0f;
            #pragma unroll
            for (int k = 0; k < 16; k++) ss += psum[threadIdx.x * 16 + k];
            roots[threadIdx.x] = powf(ss, 0.2f);
        }
        __syncthreads();
        if (threadIdx.x == 0) {
            float acc = 0.0f;
            #pragma unroll
            for (int i = 0; i < 2 * BATCH; i++) acc += roots[i];
            out[0] = acc / (float)BATCH;
            g_ticket = 0;   // reset for next graph replay (deterministic)
        }
    }
}

extern "C" void kernel_launch(void* const* d_in, const int* in_sizes, int n_in,
                              void* d_out, int out_size)
{
    const float* x = (const float*)d_in[0];
    const float* y = (const float*)d_in[1];
    float* out = (float*)d_out;

    dim3 grid(QCHUNKS_MAIN * SPLITS, BATCH, 2);   // 128 x 8 x 2 = 2048 blocks
    chamfer_main<<<grid, BLOCK>>>(x, y);

    dim3 cgrid(QCHUNKS, BATCH, 2);                // 512 x 8 x 2 = 8192 blocks
    combine_kernel<<<cgrid, 32 * CQ>>>(x, y, out);
}

// round 14
// speedup vs baseline: 1.2830x; 1.2830x over previous
#include <cuda_runtime.h>
#include <math.h>

#define BATCH   8
#define NPTS    4096
#define SPLITS  16
#define SCAND   (NPTS / SPLITS)   // 256 candidates per split = one tile
#define TILE    256
#define BLOCK   64
#define Q       8                 // queries per thread
#define QPB     (BLOCK * Q)       // 512 queries per block
#define QCHUNKS_MAIN (NPTS / QPB) // 8
#define CBLOCK  128               // combine threads per block
#define QCHUNKS (NPTS / CBLOCK)   // 32 combine chunks per (dir,b)
#define NCOMBINE (QCHUNKS * BATCH * 2)  // 512 combine blocks
#define QTOTAL  (2 * BATCH * NPTS)      // 65536 queries overall

// Scratch (static device arrays; no allocation allowed)
// TRANSPOSED layout: g_pack[split][global_query] -> combine's split-min loads
// are lane-coalesced (256B/instr) instead of 32-sector scatters.
__device__ unsigned long long g_pack[SPLITS * QTOTAL];
__device__ float g_part[NCOMBINE];   // per-chunk |diff|^5 sums
__device__ unsigned int g_ticket;    // zero-init, self-resetting

// Order-preserving float -> uint32 map (monotone for all finite floats).
static __device__ __forceinline__ unsigned int fmap(float f) {
    unsigned int u = __float_as_uint(f);
    return (u & 0x80000000u) ? ~u : (u | 0x80000000u);
}
static __device__ __forceinline__ float funmap(unsigned int m) {
    return __uint_as_float((m & 0x80000000u) ? (m & 0x7FFFFFFFu) : ~m);
}

// Bit-exact rescore (identical fmaf sequence everywhere it is evaluated).
static __device__ __forceinline__ float score(float cx, float cy, float cz,
                                              float nqx, float nqy, float nqz) {
    float h = 0.5f * fmaf(cx, cx, fmaf(cy, cy, cz * cz));
    return fmaf(nqx, cx, fmaf(nqy, cy, fmaf(nqz, cz, h)));
}

// Main: each thread owns 8 queries, scans this block's 256-candidate split.
// Objective: h - q.c, h = 0.5|c|^2 (|q|^2 dropped, argmin-invariant).
// Writes one packed u64 per (query, split): [mapped score | 32-group base].
// Identical to the proven floor kernel except the transposed store index.
__global__ void __launch_bounds__(BLOCK) chamfer_main(
    const float* __restrict__ x, const float* __restrict__ y)
{
    const int qchunk = blockIdx.x >> 4;    // 0..7
    const int split  = blockIdx.x & 15;    // 0..15
    const int b   = blockIdx.y;
    const int dir = blockIdx.z;
    const float* q  = (dir == 0) ? x : y;
    const float* db = (dir == 0) ? y : x;
    const float* qb  = q  + (size_t)b * NPTS * 3;
    const float* dbb = db + (size_t)b * NPTS * 3;

    float nqx[Q], nqy[Q], nqz[Q];
    #pragma unroll
    for (int k = 0; k < Q; k++) {
        const int qi = qchunk * QPB + threadIdx.x + k * BLOCK;
        nqx[k] = -qb[qi*3+0];
        nqy[k] = -qb[qi*3+1];
        nqz[k] = -qb[qi*3+2];
    }

    __shared__ float4 sh[TILE];

    const int cbeg = split * SCAND;
    #pragma unroll
    for (int k = 0; k < TILE / BLOCK; k++) {
        const int cl = threadIdx.x + k * BLOCK;
        const int c  = cbeg + cl;
        float cx = dbb[c*3+0], cy = dbb[c*3+1], cz = dbb[c*3+2];
        sh[cl] = make_float4(cx, cy, cz, 0.5f * fmaf(cx, cx, fmaf(cy, cy, cz * cz)));
    }
    __syncthreads();

    float best[Q];
    int   base[Q];
    #pragma unroll
    for (int k = 0; k < Q; k++) { best[k] = 3.4e38f; base[k] = cbeg; }

    #pragma unroll
    for (int g = 0; g < TILE / 32; g++) {
        float prev[Q];
        #pragma unroll
        for (int k = 0; k < Q; k++) prev[k] = best[k];
        #pragma unroll 8
        for (int j = 0; j < 32; j++) {
            float4 c = sh[g * 32 + j];   // broadcast LDS.128, feeds 8 chains
            #pragma unroll
            for (int k = 0; k < Q; k++)
                best[k] = fminf(best[k],
                    fmaf(nqx[k], c.x, fmaf(nqy[k], c.y, fmaf(nqz[k], c.z, c.w))));
        }
        const int gb = cbeg + g * 32;
        #pragma unroll
        for (int k = 0; k < Q; k++)
            if (best[k] < prev[k]) base[k] = gb;   // strict <: earliest group wins
    }

    const int qs = (dir * BATCH + b) * NPTS;
    #pragma unroll
    for (int k = 0; k < Q; k++) {
        const int qi = qchunk * QPB + threadIdx.x + k * BLOCK;
        // Transposed: [split][global query]; 512 consecutive queries per block
        // -> stores remain fully coalesced.
        g_pack[(size_t)split * QTOTAL + qs + qi] =
            ((unsigned long long)fmap(best[k]) << 32) | (unsigned int)base[k];
    }
}

// Combine: split-min via 16 COALESCED, independent LDG.64 (transposed layout;
// lane-adjacent queries adjacent in memory -> 256B/instr, MLP=16). Equal score
// bits -> smaller base = earlier split = first-min. Then warp-cooperative
// ballot rescan (R10 scheme): round w rescans lane-w's winning 32-group, lane
// j scores candidate base_w+j (coalesced 384B), ballot+ffs -> first exact
// match. NN gather, per-chunk reduction; LAST block (ticket) folds out[0].
__global__ void __launch_bounds__(CBLOCK) combine_kernel(
    const float* __restrict__ x, const float* __restrict__ y,
    float* __restrict__ out)
{
    const int chunk = blockIdx.x;
    const int b   = blockIdx.y;
    const int dir = blockIdx.z;
    const int qi  = chunk * CBLOCK + threadIdx.x;
    const int lane = threadIdx.x & 31;
    const int wbase = threadIdx.x & ~31;
    const float* q  = (dir == 0) ? x : y;
    const float* db = (dir == 0) ? y : x;
    const float* qb  = q  + (size_t)b * NPTS * 3;
    const float* dbb = db + (size_t)b * NPTS * 3;

    // Coalesced split-min: 16 independent strided loads.
    const int gq = (dir * BATCH + b) * NPTS + qi;
    unsigned long long w = 0xFFFFFFFFFFFFFFFFull;
    #pragma unroll
    for (int s = 0; s < SPLITS; s++) {
        unsigned long long v = g_pack[(size_t)s * QTOTAL + gq];
        w = (v < w) ? v : w;
    }
    const float bb  = funmap((unsigned int)(w >> 32));
    const int  base = (int)(w & 0xFFFFFFFFu);

    const float qx = qb[qi*3+0], qy = qb[qi*3+1], qz = qb[qi*3+2];

    // Park per-query records in shared for intra-warp broadcast.
    __shared__ float4 sQ[CBLOCK];   // (nqx, nqy, nqz, bb)
    __shared__ int    sB[CBLOCK];   // 32-group base
    sQ[threadIdx.x] = make_float4(-qx, -qy, -qz, bb);
    sB[threadIdx.x] = base;
    __syncwarp();

    int bi = base;
    #pragma unroll 4
    for (int ws = 0; ws < 32; ws++) {
        const float4 r  = sQ[wbase + ws];   // LDS.128 broadcast
        const int    bw = sB[wbase + ws];   // LDS broadcast
        const int c = bw + lane;
        // Coalesced: warp covers candidates bw..bw+31 (384 contiguous bytes).
        float d = score(dbb[c*3+0], dbb[c*3+1], dbb[c*3+2], r.x, r.y, r.z);
        unsigned int mask = __ballot_sync(0xFFFFFFFFu, d == r.w);
        // mask != 0 guaranteed (bit-exact recompute). Smallest j = first min.
        if (lane == ws) bi = bw + (__ffs(mask) - 1);
    }

    float nx = dbb[bi*3+0], ny = dbb[bi*3+1], nz = dbb[bi*3+2];
    float ax = fabsf(qx - nx), ay = fabsf(qy - ny), az = fabsf(qz - nz);
    float ax2 = ax * ax, ay2 = ay * ay, az2 = az * az;
    float v = ax2 * ax2 * ax + ay2 * ay2 * ay + az2 * az2 * az;

    __shared__ float red[CBLOCK];
    red[threadIdx.x] = v;
    __syncthreads();
    #pragma unroll
    for (int stride = CBLOCK / 2; stride >= 32; stride >>= 1) {
        if (threadIdx.x < stride) red[threadIdx.x] += red[threadIdx.x + stride];
        __syncthreads();
    }
    __shared__ bool s_last;
    if (threadIdx.x < 32) {
        float r = red[threadIdx.x];
        #pragma unroll
        for (int off = 16; off > 0; off >>= 1)
            r += __shfl_down_sync(0xFFFFFFFF, r, off);
        if (threadIdx.x == 0) {
            g_part[(dir * BATCH + b) * QCHUNKS + chunk] = r;
            __threadfence();
            unsigned int t = atomicAdd(&g_ticket, 1u);
            s_last = (t == NCOMBINE - 1);
        }
    }
    __syncthreads();

    if (s_last) {
        // Final reduction, fused into the last-arriving block.
        __shared__ float sp[NCOMBINE];
        __shared__ float roots[2 * BATCH];
        #pragma unroll
        for (int k = 0; k < NCOMBINE / CBLOCK; k++)
            sp[threadIdx.x + k * CBLOCK] = g_part[threadIdx.x + k * CBLOCK];
        __syncthreads();
        if (threadIdx.x < 2 * BATCH) {
            float s = 0.0f;
            #pragma unroll
            for (int c = 0; c < QCHUNKS; c++) s += sp[threadIdx.x * QCHUNKS + c];
            roots[threadIdx.x] = powf(s, 0.2f);
        }
        __syncthreads();
        if (threadIdx.x == 0) {
            float acc = 0.0f;
            #pragma unroll
            for (int i = 0; i < 2 * BATCH; i++) acc += roots[i];
            out[0] = acc / (float)BATCH;
            g_ticket = 0;   // reset for next graph replay (deterministic)
        }
    }
}

extern "C" void kernel_launch(void* const* d_in, const int* in_sizes, int n_in,
                              void* d_out, int out_size)
{
    const float* x = (const float*)d_in[0];
    const float* y = (const float*)d_in[1];
    float* out = (float*)d_out;

    dim3 grid(QCHUNKS_MAIN * SPLITS, BATCH, 2);   // 128 x 8 x 2 = 2048 blocks
    chamfer_main<<<grid, BLOCK>>>(x, y);

    dim3 cgrid(QCHUNKS, BATCH, 2);                // 32 x 8 x 2 = 512 blocks
    combine_kernel<<<cgrid, CBLOCK>>>(x, y, out);
}

// round 15
// speedup vs baseline: 1.2878x; 1.0037x over previous
#include <cuda_runtime.h>
#include <math.h>

#define BATCH   8
#define NPTS    4096
#define SPLITS  16
#define SCAND   (NPTS / SPLITS)   // 256 candidates per split = one tile
#define TILE    256
#define BLOCK   64
#define Q       8                 // queries per thread
#define QPB     (BLOCK * Q)       // 512 queries per block
#define QCHUNKS_MAIN (NPTS / QPB) // 8
#define CBLOCK  128               // combine threads per block
#define QCHUNKS (NPTS / CBLOCK)   // 32 combine chunks per (dir,b)
#define NCOMBINE (QCHUNKS * BATCH * 2)  // 512 combine blocks
#define QTOTAL  (2 * BATCH * NPTS)      // 65536 queries overall

// Scratch (static device arrays; no allocation allowed)
// Transposed layout: g_pack[split][global_query] -> combine's split-min loads
// are lane-coalesced (256B/instr) instead of 32-sector scatters.
__device__ unsigned long long g_pack[SPLITS * QTOTAL];
__device__ float g_part[NCOMBINE];   // per-chunk |diff|^5 sums
__device__ unsigned int g_ticket;    // zero-init, self-resetting

// Order-preserving float -> uint32 map (monotone for all finite floats).
static __device__ __forceinline__ unsigned int fmap(float f) {
    unsigned int u = __float_as_uint(f);
    return (u & 0x80000000u) ? ~u : (u | 0x80000000u);
}
static __device__ __forceinline__ float funmap(unsigned int m) {
    return __uint_as_float((m & 0x80000000u) ? (m & 0x7FFFFFFFu) : ~m);
}

// Bit-exact rescore (identical fmaf sequence everywhere it is evaluated).
static __device__ __forceinline__ float score(float cx, float cy, float cz,
                                              float nqx, float nqy, float nqz) {
    float h = 0.5f * fmaf(cx, cx, fmaf(cy, cy, cz * cz));
    return fmaf(nqx, cx, fmaf(nqy, cy, fmaf(nqz, cz, h)));
}

// Main: each thread owns 8 queries, scans this block's 256-candidate split.
// Objective: h - q.c, h = 0.5|c|^2 (|q|^2 dropped, argmin-invariant).
// Writes one packed u64 per (query, split): [mapped score | 32-group base].
// BYTE-IDENTICAL to the proven round-14 kernel (fma-pipe floor).
__global__ void __launch_bounds__(BLOCK) chamfer_main(
    const float* __restrict__ x, const float* __restrict__ y)
{
    const int qchunk = blockIdx.x >> 4;    // 0..7
    const int split  = blockIdx.x & 15;    // 0..15
    const int b   = blockIdx.y;
    const int dir = blockIdx.z;
    const float* q  = (dir == 0) ? x : y;
    const float* db = (dir == 0) ? y : x;
    const float* qb  = q  + (size_t)b * NPTS * 3;
    const float* dbb = db + (size_t)b * NPTS * 3;

    float nqx[Q], nqy[Q], nqz[Q];
    #pragma unroll
    for (int k = 0; k < Q; k++) {
        const int qi = qchunk * QPB + threadIdx.x + k * BLOCK;
        nqx[k] = -qb[qi*3+0];
        nqy[k] = -qb[qi*3+1];
        nqz[k] = -qb[qi*3+2];
    }

    __shared__ float4 sh[TILE];

    const int cbeg = split * SCAND;
    #pragma unroll
    for (int k = 0; k < TILE / BLOCK; k++) {
        const int cl = threadIdx.x + k * BLOCK;
        const int c  = cbeg + cl;
        float cx = dbb[c*3+0], cy = dbb[c*3+1], cz = dbb[c*3+2];
        sh[cl] = make_float4(cx, cy, cz, 0.5f * fmaf(cx, cx, fmaf(cy, cy, cz * cz)));
    }
    __syncthreads();

    float best[Q];
    int   base[Q];
    #pragma unroll
    for (int k = 0; k < Q; k++) { best[k] = 3.4e38f; base[k] = cbeg; }

    #pragma unroll
    for (int g = 0; g < TILE / 32; g++) {
        float prev[Q];
        #pragma unroll
        for (int k = 0; k < Q; k++) prev[k] = best[k];
        #pragma unroll 8
        for (int j = 0; j < 32; j++) {
            float4 c = sh[g * 32 + j];   // broadcast LDS.128, feeds 8 chains
            #pragma unroll
            for (int k = 0; k < Q; k++)
                best[k] = fminf(best[k],
                    fmaf(nqx[k], c.x, fmaf(nqy[k], c.y, fmaf(nqz[k], c.z, c.w))));
        }
        const int gb = cbeg + g * 32;
        #pragma unroll
        for (int k = 0; k < Q; k++)
            if (best[k] < prev[k]) base[k] = gb;   // strict <: earliest group wins
    }

    const int qs = (dir * BATCH + b) * NPTS;
    #pragma unroll
    for (int k = 0; k < Q; k++) {
        const int qi = qchunk * QPB + threadIdx.x + k * BLOCK;
        g_pack[(size_t)split * QTOTAL + qs + qi] =
            ((unsigned long long)fmap(best[k]) << 32) | (unsigned int)base[k];
    }
}

// Combine: coalesced split-min (16 independent LDG.64; equal score bits ->
// smaller base = earlier split = first-min). Warp-cooperative ballot rescan,
// SOFTWARE-PIPELINED: round ws+1's loads are issued before round ws's ballot,
// hiding the LDG round-trip. NN coords are extracted IN-ROUND via shfl from
// the first-hit lane (kills the scattered final gather). Per-chunk reduction;
// LAST block (ticket) folds out[0].
__global__ void __launch_bounds__(CBLOCK) combine_kernel(
    const float* __restrict__ x, const float* __restrict__ y,
    float* __restrict__ out)
{
    const int chunk = blockIdx.x;
    const int b   = blockIdx.y;
    const int dir = blockIdx.z;
    const int qi  = chunk * CBLOCK + threadIdx.x;
    const int lane = threadIdx.x & 31;
    const int wbase = threadIdx.x & ~31;
    const float* q  = (dir == 0) ? x : y;
    const float* db = (dir == 0) ? y : x;
    const float* qb  = q  + (size_t)b * NPTS * 3;
    const float* dbb = db + (size_t)b * NPTS * 3;

    // Coalesced split-min: 16 independent strided loads.
    const int gq = (dir * BATCH + b) * NPTS + qi;
    unsigned long long w = 0xFFFFFFFFFFFFFFFFull;
    #pragma unroll
    for (int s = 0; s < SPLITS; s++) {
        unsigned long long v = g_pack[(size_t)s * QTOTAL + gq];
        w = (v < w) ? v : w;
    }
    const float bb  = funmap((unsigned int)(w >> 32));
    const int  base = (int)(w & 0xFFFFFFFFu);

    const float qx = qb[qi*3+0], qy = qb[qi*3+1], qz = qb[qi*3+2];

    // Park per-query records in shared for intra-warp broadcast.
    __shared__ float4 sQ[CBLOCK];   // (nqx, nqy, nqz, bb)
    __shared__ int    sB[CBLOCK];   // 32-group base
    sQ[threadIdx.x] = make_float4(-qx, -qy, -qz, bb);
    sB[threadIdx.x] = base;
    __syncwarp();

    float nx = 0.f, ny = 0.f, nz = 0.f;

    // Pipelined ballot rescan: stage (r,c coords) for round ws+1 while
    // resolving round ws. Round ws serves query of lane ws.
    float4 r  = sQ[wbase];
    int    c  = sB[wbase] + lane;
    float  cx = dbb[c*3+0], cy = dbb[c*3+1], cz = dbb[c*3+2];

    #pragma unroll 4
    for (int ws = 0; ws < 32; ws++) {
        float4 rn; float cxn, cyn, czn;
        if (ws < 31) {
            rn = sQ[wbase + ws + 1];
            const int cn = sB[wbase + ws + 1] + lane;
            cxn = dbb[cn*3+0]; cyn = dbb[cn*3+1]; czn = dbb[cn*3+2];
        }
        float d = score(cx, cy, cz, r.x, r.y, r.z);
        unsigned int mask = __ballot_sync(0xFFFFFFFFu, d == r.w);
        const int first = __ffs(mask) - 1;   // >=0 guaranteed (bit-exact)
        // Winner lane's coords -> owner lane (first exact match = first min).
        float fx = __shfl_sync(0xFFFFFFFFu, cx, first);
        float fy = __shfl_sync(0xFFFFFFFFu, cy, first);
        float fz = __shfl_sync(0xFFFFFFFFu, cz, first);
        if (lane == ws) { nx = fx; ny = fy; nz = fz; }
        r = rn; cx = cxn; cy = cyn; cz = czn;
    }

    float ax = fabsf(qx - nx), ay = fabsf(qy - ny), az = fabsf(qz - nz);
    float ax2 = ax * ax, ay2 = ay * ay, az2 = az * az;
    float v = ax2 * ax2 * ax + ay2 * ay2 * ay + az2 * az2 * az;

    __shared__ float red[CBLOCK];
    red[threadIdx.x] = v;
    __syncthreads();
    #pragma unroll
    for (int stride = CBLOCK / 2; stride >= 32; stride >>= 1) {
        if (threadIdx.x < stride) red[threadIdx.x] += red[threadIdx.x + stride];
        __syncthreads();
    }
    __shared__ bool s_last;
    if (threadIdx.x < 32) {
        float rr = red[threadIdx.x];
        #pragma unroll
        for (int off = 16; off > 0; off >>= 1)
            rr += __shfl_down_sync(0xFFFFFFFF, rr, off);
        if (threadIdx.x == 0) {
            g_part[(dir * BATCH + b) * QCHUNKS + chunk] = rr;
            __threadfence();
            unsigned int t = atomicAdd(&g_ticket, 1u);
            s_last = (t == NCOMBINE - 1);
        }
    }
    __syncthreads();

    if (s_last) {
        // Final reduction, fused into the last-arriving block.
        __shared__ float sp[NCOMBINE];
        __shared__ float roots[2 * BATCH];
        #pragma unroll
        for (int k = 0; k < NCOMBINE / CBLOCK; k++)
            sp[threadIdx.x + k * CBLOCK] = g_part[threadIdx.x + k * CBLOCK];
        __syncthreads();
        if (threadIdx.x < 2 * BATCH) {
            float s = 0.0f;
            #pragma unroll
            for (int c2 = 0; c2 < QCHUNKS; c2++) s += sp[threadIdx.x * QCHUNKS + c2];
            roots[threadIdx.x] = powf(s, 0.2f);
        }
        __syncthreads();
        if (threadIdx.x == 0) {
            float acc = 0.0f;
            #pragma unroll
            for (int i = 0; i < 2 * BATCH; i++) acc += roots[i];
            out[0] = acc / (float)BATCH;
            g_ticket = 0;   // reset for next graph replay (deterministic)
        }
    }
}

extern "C" void kernel_launch(void* const* d_in, const int* in_sizes, int n_in,
                              void* d_out, int out_size)
{
    const float* x = (const float*)d_in[0];
    const float* y = (const float*)d_in[1];
    float* out = (float*)d_out;

    dim3 grid(QCHUNKS_MAIN * SPLITS, BATCH, 2);   // 128 x 8 x 2 = 2048 blocks
    chamfer_main<<<grid, BLOCK>>>(x, y);

    dim3 cgrid(QCHUNKS, BATCH, 2);                // 32 x 8 x 2 = 512 blocks
    combine_kernel<<<cgrid, CBLOCK>>>(x, y, out);
}